// round 8
// baseline (speedup 1.0000x reference)
#include <cuda_runtime.h>
#include <cuda_fp16.h>
#include <cstdint>
#include <math.h>

#define BB 4
#define SS 4096
#define DD 256
#define ROWS (BB*SS)

// Scratch (device globals — no allocation in kernel_launch)
__device__ __half g_qh[ROWS*DD];
__device__ __half g_kh[ROWS*DD];
__device__ __half g_vh[ROWS*DD];
__device__ float  g_ao[ROWS*DD];
__device__ __half g_hh[ROWS*DD];
__device__ __half g_th[ROWS*DD];
__device__ float  g_t2[ROWS*DD];
__device__ float  g_qn[ROWS];     // per-row |q_hat|_2
__device__ int    g_km[BB];       // per-batch max |k|_2 (float bits, positive)

// ---------------------------------------------------------------------------
// mma / ldmatrix / cp.async helpers
// ---------------------------------------------------------------------------
__device__ __forceinline__ uint32_t smem_u32(const void* p) {
    return (uint32_t)__cvta_generic_to_shared(p);
}
__device__ __forceinline__ void ldsm4(uint32_t& r0, uint32_t& r1, uint32_t& r2, uint32_t& r3, uint32_t a) {
    asm volatile("ldmatrix.sync.aligned.m8n8.x4.shared.b16 {%0,%1,%2,%3},[%4];"
                 : "=r"(r0), "=r"(r1), "=r"(r2), "=r"(r3) : "r"(a));
}
__device__ __forceinline__ void ldsm4t(uint32_t& r0, uint32_t& r1, uint32_t& r2, uint32_t& r3, uint32_t a) {
    asm volatile("ldmatrix.sync.aligned.m8n8.x4.trans.shared.b16 {%0,%1,%2,%3},[%4];"
                 : "=r"(r0), "=r"(r1), "=r"(r2), "=r"(r3) : "r"(a));
}
__device__ __forceinline__ void mma16816(float* c, uint32_t a0, uint32_t a1, uint32_t a2, uint32_t a3,
                                         uint32_t b0, uint32_t b1) {
    asm volatile("mma.sync.aligned.m16n8k16.row.col.f32.f16.f16.f32 "
                 "{%0,%1,%2,%3},{%4,%5,%6,%7},{%8,%9},{%0,%1,%2,%3};"
                 : "+f"(c[0]), "+f"(c[1]), "+f"(c[2]), "+f"(c[3])
                 : "r"(a0), "r"(a1), "r"(a2), "r"(a3), "r"(b0), "r"(b1));
}
__device__ __forceinline__ uint32_t packh2(float lo, float hi) {
    __half2 h = __floats2half2_rn(lo, hi);
    return *reinterpret_cast<uint32_t*>(&h);
}
__device__ __forceinline__ void cpa16(uint32_t dst, const void* src) {
    asm volatile("cp.async.cg.shared.global [%0], [%1], 16;" :: "r"(dst), "l"(src));
}
__device__ __forceinline__ void cpa_commit() {
    asm volatile("cp.async.commit_group;");
}
template<int N>
__device__ __forceinline__ void cpa_wait() {
    asm volatile("cp.async.wait_group %0;" :: "n"(N));
}

// ---------------------------------------------------------------------------
// Tensor-core GEMM: C[M][256] = A[M][256] @ W[256][256]^T + bias (unchanged)
// ---------------------------------------------------------------------------
#define GLDH 72

template<typename TA, bool RELU, bool HALF_OUT>
__global__ __launch_bounds__(256) void hgemm_k(const TA* __restrict__ A,
                                               const float* __restrict__ W,
                                               const float* __restrict__ bias,
                                               void* __restrict__ Cv,
                                               float scale) {
    __shared__ __half sA[128 * GLDH];
    __shared__ __half sW[128 * GLDH];
    const int tid  = threadIdx.x;
    const int warp = tid >> 5, lane = tid & 31;
    const int wm = warp & 3;
    const int wn = warp >> 2;
    const int m0 = blockIdx.y * 128;
    const int n0 = blockIdx.x * 128;

    float acc[2][8][4] = {};

    const uint32_t aAddr = smem_u32(sA + (wm * 32 + (lane & 15)) * GLDH + (lane >> 4) * 8);
    const uint32_t wAddr = smem_u32(sW + (wn * 64 + (lane & 7) + ((lane >> 4) & 1) * 8) * GLDH + ((lane >> 3) & 1) * 8);

    for (int kc = 0; kc < 256; kc += 64) {
        for (int i = tid; i < 1024; i += 256) {
            int r = i >> 3, c8 = (i & 7) * 8;
            if (sizeof(TA) == 2) {
                *(uint4*)(sA + r * GLDH + c8) =
                    *(const uint4*)((const __half*)A + (size_t)(m0 + r) * 256 + kc + c8);
            } else {
                const float* ap = (const float*)A + (size_t)(m0 + r) * 256 + kc + c8;
                float4 f0 = *(const float4*)ap, f1 = *(const float4*)(ap + 4);
                uint4 u;
                u.x = packh2(f0.x, f0.y); u.y = packh2(f0.z, f0.w);
                u.z = packh2(f1.x, f1.y); u.w = packh2(f1.z, f1.w);
                *(uint4*)(sA + r * GLDH + c8) = u;
            }
            const float* wp = W + (size_t)(n0 + r) * 256 + kc + c8;
            float4 g0 = *(const float4*)wp, g1 = *(const float4*)(wp + 4);
            uint4 uw;
            uw.x = packh2(g0.x, g0.y); uw.y = packh2(g0.z, g0.w);
            uw.z = packh2(g1.x, g1.y); uw.w = packh2(g1.z, g1.w);
            *(uint4*)(sW + r * GLDH + c8) = uw;
        }
        __syncthreads();

        #pragma unroll
        for (int kk = 0; kk < 4; kk++) {
            uint32_t a[2][4];
            ldsm4(a[0][0], a[0][1], a[0][2], a[0][3], aAddr + kk * 32);
            ldsm4(a[1][0], a[1][1], a[1][2], a[1][3], aAddr + 16 * GLDH * 2 + kk * 32);
            #pragma unroll
            for (int j = 0; j < 4; j++) {
                uint32_t b0, b1, b2, b3;
                ldsm4(b0, b1, b2, b3, wAddr + j * 16 * GLDH * 2 + kk * 32);
                mma16816(acc[0][2 * j],     a[0][0], a[0][1], a[0][2], a[0][3], b0, b1);
                mma16816(acc[0][2 * j + 1], a[0][0], a[0][1], a[0][2], a[0][3], b2, b3);
                mma16816(acc[1][2 * j],     a[1][0], a[1][1], a[1][2], a[1][3], b0, b1);
                mma16816(acc[1][2 * j + 1], a[1][0], a[1][1], a[1][2], a[1][3], b2, b3);
            }
        }
        __syncthreads();
    }

    const int g = lane >> 2, qd = lane & 3;
    #pragma unroll
    for (int s = 0; s < 2; s++) {
        int row0 = m0 + wm * 32 + s * 16 + g;
        #pragma unroll
        for (int j = 0; j < 8; j++) {
            int col = n0 + wn * 64 + j * 8 + qd * 2;
            float b0 = bias[col], b1 = bias[col + 1];
            float v00 = acc[s][j][0] + b0, v01 = acc[s][j][1] + b1;
            float v10 = acc[s][j][2] + b0, v11 = acc[s][j][3] + b1;
            if (RELU) {
                v00 = fmaxf(v00, 0.0f); v01 = fmaxf(v01, 0.0f);
                v10 = fmaxf(v10, 0.0f); v11 = fmaxf(v11, 0.0f);
            }
            if (HALF_OUT) {
                *(uint32_t*)((__half*)Cv + (size_t)row0 * 256 + col)      = packh2(v00 * scale, v01 * scale);
                *(uint32_t*)((__half*)Cv + (size_t)(row0 + 8) * 256 + col) = packh2(v10 * scale, v11 * scale);
            } else {
                float2 f0 = {v00, v01}, f1 = {v10, v11};
                *(float2*)((float*)Cv + (size_t)row0 * 256 + col)      = f0;
                *(float2*)((float*)Cv + (size_t)(row0 + 8) * 256 + col) = f1;
            }
        }
    }
}

// ---------------------------------------------------------------------------
// Row L2 norms. One warp per row of 256 halfs.
// KMAX: also atomicMax the per-batch max row norm (positive floats as ints).
// ---------------------------------------------------------------------------
template<bool KMAX>
__global__ __launch_bounds__(256) void norm_k(const __half* __restrict__ X,
                                              float* __restrict__ nrm,
                                              int* __restrict__ kmax) {
    int row  = (blockIdx.x * blockDim.x + threadIdx.x) >> 5;
    int lane = threadIdx.x & 31;
    const __half* xr = X + (size_t)row * DD;
    float s = 0.0f;
    #pragma unroll
    for (int t = 0; t < 8; t++) {
        float v = __half2float(xr[t * 32 + lane]);
        s += v * v;
    }
    #pragma unroll
    for (int o = 16; o; o >>= 1) s += __shfl_xor_sync(0xffffffffu, s, o);
    if (lane == 0) {
        float n = sqrtf(s);
        if (KMAX) atomicMax(&kmax[row / SS], __float_as_int(n));
        else      nrm[row] = n;
    }
}

// ---------------------------------------------------------------------------
// Flash attention, fp16 tensor-core, cp.async double-buffered K/V.
// Round 8: NO online softmax. Per-row static bound M = |q_hat| * max|k|
// (Cauchy-Schwarz) guarantees s <= M; p = 2^((s-M)*log2e + 13.9).
// The +13.9 bias keeps p in fp16-normal range and cancels in O/l.
// l accumulates lane-locally; single reduction at the end.
// ---------------------------------------------------------------------------
#define LDH 264
#define BRQ 128
#define QTILEH (BRQ * LDH)
#define TILEH (64 * LDH)
#define STGH  (2 * TILEH)
#define FLASH_SMEM ((QTILEH + 2 * STGH) * (int)sizeof(__half))
#define L2E 1.44269504f

__global__ __launch_bounds__(256, 1) void flash_h(const __half* __restrict__ Q,
                                                  const __half* __restrict__ K,
                                                  const __half* __restrict__ V,
                                                  const float* __restrict__ qn,
                                                  const int* __restrict__ km,
                                                  float* __restrict__ O) {
    extern __shared__ __half sm[];
    __half* sQ  = sm;
    __half* sK0 = sm + QTILEH;
    __half* sV0 = sK0 + TILEH;

    const int b  = blockIdx.y;
    const int q0 = blockIdx.x * BRQ;
    const int tid = threadIdx.x;
    const int warp = tid >> 5;
    const int lane = tid & 31;
    const int g  = lane >> 2;
    const int qd = lane & 3;

    const __half* Qb = Q + ((size_t)b * SS + q0) * DD;
    const __half* Kb = K + (size_t)b * SS * DD;
    const __half* Vb = V + (size_t)b * SS * DD;

    // Static exponent biases for this warp's two rows.
    const float kmax = __int_as_float(km[b]);
    const int gr0 = b * SS + q0 + warp * 16 + g;
    const float e0 = fmaf(-qn[gr0]     * kmax, L2E, 13.9f);
    const float e1 = fmaf(-qn[gr0 + 8] * kmax, L2E, 13.9f);

    // Load Q tile via cp.async (merged into group 0)
    for (int c = tid; c < 4096; c += 256) {
        int r = c >> 5, co = (c & 31) * 8;
        cpa16(smem_u32(sQ + r * LDH + co), Qb + (size_t)r * 256 + co);
    }

    // prologue: stage 0 <- tile 0
    {
        const uint32_t kDst = smem_u32(sK0);
        for (int c = tid; c < 2048; c += 256) {
            int r = c >> 5, co = (c & 31) * 8;
            cpa16(kDst + (r * LDH + co) * 2,             Kb + (size_t)r * 256 + co);
            cpa16(kDst + (TILEH + r * LDH + co) * 2,     Vb + (size_t)r * 256 + co);
        }
        cpa_commit();
    }

    float o[32][4];
    #pragma unroll
    for (int t = 0; t < 32; t++) { o[t][0] = 0; o[t][1] = 0; o[t][2] = 0; o[t][3] = 0; }
    float l0 = 0.0f, l1 = 0.0f;

    const uint32_t aBase  = smem_u32(sQ + (warp * 16 + (lane & 15)) * LDH + (lane >> 4) * 8);
    const uint32_t kBase0 = smem_u32(sK0 + ((lane & 7) + ((lane >> 4) & 1) * 8) * LDH + ((lane >> 3) & 1) * 8);
    const uint32_t vBase0 = smem_u32(sV0 + (lane & 15) * LDH + (lane >> 4) * 8);
    const uint32_t kDst0  = smem_u32(sK0);

    for (int ti = 0; ti < SS / 64; ti++) {
        if (ti + 1 < SS / 64) {
            const uint32_t kDst = kDst0 + ((ti + 1) & 1) * STGH * 2;
            const __half* Kn = Kb + (size_t)(ti + 1) * 64 * 256;
            const __half* Vn = Vb + (size_t)(ti + 1) * 64 * 256;
            for (int c = tid; c < 2048; c += 256) {
                int r = c >> 5, co = (c & 31) * 8;
                cpa16(kDst + (r * LDH + co) * 2,         Kn + (size_t)r * 256 + co);
                cpa16(kDst + (TILEH + r * LDH + co) * 2, Vn + (size_t)r * 256 + co);
            }
        }
        cpa_commit();
        cpa_wait<1>();
        __syncthreads();

        const uint32_t kBase = kBase0 + (ti & 1) * STGH * 2;
        const uint32_t vBase = vBase0 + (ti & 1) * STGH * 2;

        // ---- S = Q K^T ----
        float s[8][4];
        #pragma unroll
        for (int j = 0; j < 8; j++) { s[j][0] = 0; s[j][1] = 0; s[j][2] = 0; s[j][3] = 0; }

        #pragma unroll
        for (int kk = 0; kk < 16; kk++) {
            uint32_t a0, a1, a2, a3;
            ldsm4(a0, a1, a2, a3, aBase + kk * 32);
            #pragma unroll
            for (int jj = 0; jj < 4; jj++) {
                uint32_t k0, k1, k2, k3;
                ldsm4(k0, k1, k2, k3, kBase + jj * 16 * LDH * 2 + kk * 32);
                mma16816(s[2 * jj],     a0, a1, a2, a3, k0, k1);
                mma16816(s[2 * jj + 1], a0, a1, a2, a3, k2, k3);
            }
        }

        // ---- softmax numerators with static bound (no max, no rescale) ----
        uint32_t pl[8], ph[8];
        #pragma unroll
        for (int j = 0; j < 8; j++) {
            float p0 = exp2f(fmaf(s[j][0], L2E, e0));
            float p1 = exp2f(fmaf(s[j][1], L2E, e0));
            float p2 = exp2f(fmaf(s[j][2], L2E, e1));
            float p3 = exp2f(fmaf(s[j][3], L2E, e1));
            l0 += p0 + p1; l1 += p2 + p3;
            pl[j] = packh2(p0, p1);
            ph[j] = packh2(p2, p3);
        }

        // ---- O += P V ----
        #pragma unroll
        for (int kk2 = 0; kk2 < 4; kk2++) {
            uint32_t a0 = pl[2 * kk2], a1 = ph[2 * kk2];
            uint32_t a2 = pl[2 * kk2 + 1], a3 = ph[2 * kk2 + 1];
            uint32_t vrow = vBase + kk2 * 16 * LDH * 2;
            #pragma unroll
            for (int nj = 0; nj < 16; nj++) {
                uint32_t v0, v1, v2, v3;
                ldsm4t(v0, v1, v2, v3, vrow + nj * 32);
                mma16816(o[2 * nj],     a0, a1, a2, a3, v0, v1);
                mma16816(o[2 * nj + 1], a0, a1, a2, a3, v2, v3);
            }
        }
        __syncthreads();
    }

    // ---- final l reduction + normalize + store ----
    l0 += __shfl_xor_sync(0xffffffffu, l0, 1);
    l0 += __shfl_xor_sync(0xffffffffu, l0, 2);
    l1 += __shfl_xor_sync(0xffffffffu, l1, 1);
    l1 += __shfl_xor_sync(0xffffffffu, l1, 2);
    float inv0 = 1.0f / l0, inv1 = 1.0f / l1;
    float* Ob0 = O + ((size_t)b * SS + q0 + warp * 16 + g) * 256;
    float* Ob1 = Ob0 + 8 * 256;
    #pragma unroll
    for (int j = 0; j < 32; j++) {
        int col = j * 8 + qd * 2;
        float2 w0 = { o[j][0] * inv0, o[j][1] * inv0 };
        float2 w1 = { o[j][2] * inv1, o[j][3] * inv1 };
        *(float2*)(Ob0 + col) = w0;
        *(float2*)(Ob1 + col) = w1;
    }
}

// ---------------------------------------------------------------------------
// LayerNorm(X + R) * g + be — one warp per row; optionally emit fp16
// ---------------------------------------------------------------------------
template<bool HALF_OUT>
__global__ __launch_bounds__(256) void ln_k(const float* __restrict__ X,
                                            const float* __restrict__ R,
                                            const float* __restrict__ g,
                                            const float* __restrict__ be,
                                            void* __restrict__ outv) {
    int row  = (blockIdx.x * blockDim.x + threadIdx.x) >> 5;
    int lane = threadIdx.x & 31;
    const float* xr = X + (size_t)row * DD;
    const float* rr = R + (size_t)row * DD;

    float v[8];
    float s = 0.0f;
    #pragma unroll
    for (int t = 0; t < 8; t++) {
        int d = t * 32 + lane;
        v[t] = xr[d] + rr[d];
        s += v[t];
    }
    #pragma unroll
    for (int o = 16; o; o >>= 1) s += __shfl_xor_sync(0xffffffffu, s, o);
    float mu = s * (1.0f / 256.0f);

    float var = 0.0f;
    #pragma unroll
    for (int t = 0; t < 8; t++) { float dv = v[t] - mu; var += dv * dv; }
    #pragma unroll
    for (int o = 16; o; o >>= 1) var += __shfl_xor_sync(0xffffffffu, var, o);
    var *= (1.0f / 256.0f);
    float rstd = rsqrtf(var + 1e-5f);

    #pragma unroll
    for (int t = 0; t < 8; t++) {
        int d = t * 32 + lane;
        float w = (v[t] - mu) * rstd * g[d] + be[d];
        if (HALF_OUT) ((__half*)outv)[(size_t)row * DD + d] = __float2half_rn(w);
        else          ((float*)outv)[(size_t)row * DD + d] = w;
    }
}

// ---------------------------------------------------------------------------
extern "C" void kernel_launch(void* const* d_in, const int* in_sizes, int n_in,
                              void* d_out, int out_size) {
    (void)in_sizes; (void)n_in; (void)out_size;
    const float* x  = (const float*)d_in[0];
    const float* Wq = (const float*)d_in[1];
    const float* bq = (const float*)d_in[2];
    const float* Wk = (const float*)d_in[3];
    const float* bk = (const float*)d_in[4];
    const float* Wv = (const float*)d_in[5];
    const float* bv = (const float*)d_in[6];
    const float* Wl = (const float*)d_in[7];
    const float* bl = (const float*)d_in[8];
    const float* g1 = (const float*)d_in[9];
    const float* be1= (const float*)d_in[10];
    const float* g2 = (const float*)d_in[11];
    const float* be2= (const float*)d_in[12];
    float* out = (float*)d_out;

    __half *gq, *gk, *gv, *ghh, *gth;
    float *gao, *gt2, *gqn;
    int *gkm;
    cudaGetSymbolAddress((void**)&gq,  g_qh);
    cudaGetSymbolAddress((void**)&gk,  g_kh);
    cudaGetSymbolAddress((void**)&gv,  g_vh);
    cudaGetSymbolAddress((void**)&gao, g_ao);
    cudaGetSymbolAddress((void**)&ghh, g_hh);
    cudaGetSymbolAddress((void**)&gth, g_th);
    cudaGetSymbolAddress((void**)&gt2, g_t2);
    cudaGetSymbolAddress((void**)&gqn, g_qn);
    cudaGetSymbolAddress((void**)&gkm, g_km);

    cudaFuncSetAttribute(flash_h, cudaFuncAttributeMaxDynamicSharedMemorySize, FLASH_SMEM);

    dim3 ggrid(DD / 128, ROWS / 128);   // (2, 128)

    hgemm_k<float, false, true ><<<ggrid, 256>>>(x, Wq, bq, gq, 0.0625f);
    hgemm_k<float, false, true ><<<ggrid, 256>>>(x, Wk, bk, gk, 1.0f);
    hgemm_k<float, false, true ><<<ggrid, 256>>>(x, Wv, bv, gv, 1.0f);

    // per-row |q_hat|, per-batch max |k|
    cudaMemsetAsync(gkm, 0, BB * sizeof(int));
    norm_k<false><<<ROWS / 8, 256>>>(gq, gqn, nullptr);
    norm_k<true ><<<ROWS / 8, 256>>>(gk, nullptr, gkm);

    flash_h<<<dim3(SS / BRQ, BB), 256, FLASH_SMEM>>>(gq, gk, gv, gqn, gkm, gao);

    ln_k<true ><<<ROWS / 8, 256>>>(x, gao, g1, be1, ghh);

    hgemm_k<__half, true,  true ><<<ggrid, 256>>>(ghh, Wl, bl, gth, 1.0f);
    hgemm_k<__half, false, false><<<ggrid, 256>>>(gth, Wl, bl, gt2, 1.0f);

    ln_k<false><<<ROWS / 8, 256>>>(x, gt2, g2, be2, out);
}

// round 10
// speedup vs baseline: 1.0943x; 1.0943x over previous
#include <cuda_runtime.h>
#include <cuda_fp16.h>
#include <cstdint>
#include <math.h>

#define BB 4
#define SS 4096
#define DD 256
#define ROWS (BB*SS)

// Scratch (device globals — no allocation in kernel_launch)
__device__ __half g_xh[ROWS*DD];          // x in fp16
__device__ __half g_w4[4*DD*DD];          // Wq|Wk|Wv|Wl in fp16
__device__ __half g_qh[ROWS*DD];
__device__ __half g_kh[ROWS*DD];
__device__ __half g_vh[ROWS*DD];
__device__ __half g_hh[ROWS*DD];          // LN1 output (fp16)
__device__ __half g_th[ROWS*DD];
__device__ float  g_t2[ROWS*DD];

// ---------------------------------------------------------------------------
// helpers
// ---------------------------------------------------------------------------
__device__ __forceinline__ uint32_t smem_u32(const void* p) {
    return (uint32_t)__cvta_generic_to_shared(p);
}
__device__ __forceinline__ void ldsm4(uint32_t& r0, uint32_t& r1, uint32_t& r2, uint32_t& r3, uint32_t a) {
    asm volatile("ldmatrix.sync.aligned.m8n8.x4.shared.b16 {%0,%1,%2,%3},[%4];"
                 : "=r"(r0), "=r"(r1), "=r"(r2), "=r"(r3) : "r"(a));
}
__device__ __forceinline__ void ldsm4t(uint32_t& r0, uint32_t& r1, uint32_t& r2, uint32_t& r3, uint32_t a) {
    asm volatile("ldmatrix.sync.aligned.m8n8.x4.trans.shared.b16 {%0,%1,%2,%3},[%4];"
                 : "=r"(r0), "=r"(r1), "=r"(r2), "=r"(r3) : "r"(a));
}
__device__ __forceinline__ void mma16816(float* c, uint32_t a0, uint32_t a1, uint32_t a2, uint32_t a3,
                                         uint32_t b0, uint32_t b1) {
    asm volatile("mma.sync.aligned.m16n8k16.row.col.f32.f16.f16.f32 "
                 "{%0,%1,%2,%3},{%4,%5,%6,%7},{%8,%9},{%0,%1,%2,%3};"
                 : "+f"(c[0]), "+f"(c[1]), "+f"(c[2]), "+f"(c[3])
                 : "r"(a0), "r"(a1), "r"(a2), "r"(a3), "r"(b0), "r"(b1));
}
__device__ __forceinline__ uint32_t packh2(float lo, float hi) {
    __half2 h = __floats2half2_rn(lo, hi);
    return *reinterpret_cast<uint32_t*>(&h);
}
__device__ __forceinline__ void cpa16(uint32_t dst, const void* src) {
    asm volatile("cp.async.cg.shared.global [%0], [%1], 16;" :: "r"(dst), "l"(src));
}
__device__ __forceinline__ void cpa_commit() { asm volatile("cp.async.commit_group;"); }
template<int N>
__device__ __forceinline__ void cpa_wait() { asm volatile("cp.async.wait_group %0;" :: "n"(N)); }

// ---------------------------------------------------------------------------
// fp32 -> fp16 converters
// ---------------------------------------------------------------------------
__global__ __launch_bounds__(256) void cvt_x(const float* __restrict__ src,
                                             __half* __restrict__ dst) {
    int i = (blockIdx.x * 256 + threadIdx.x) * 8;
    float4 a = *(const float4*)(src + i);
    float4 b = *(const float4*)(src + i + 4);
    uint4 u;
    u.x = packh2(a.x, a.y); u.y = packh2(a.z, a.w);
    u.z = packh2(b.x, b.y); u.w = packh2(b.z, b.w);
    *(uint4*)(dst + i) = u;
}

__global__ __launch_bounds__(256) void cvt_w(const float* __restrict__ w0,
                                             const float* __restrict__ w1,
                                             const float* __restrict__ w2,
                                             const float* __restrict__ w3,
                                             __half* __restrict__ dst) {
    int y = blockIdx.y;
    const float* s = (y == 0) ? w0 : (y == 1) ? w1 : (y == 2) ? w2 : w3;
    int i = (blockIdx.x * 256 + threadIdx.x) * 8;
    float4 a = *(const float4*)(s + i);
    float4 b = *(const float4*)(s + i + 4);
    uint4 u;
    u.x = packh2(a.x, a.y); u.y = packh2(a.z, a.w);
    u.z = packh2(b.x, b.y); u.w = packh2(b.z, b.w);
    *(uint4*)(dst + y * DD * DD + i) = u;
}

// ---------------------------------------------------------------------------
// fp16 tensor-core GEMM, cp.async double-buffered over 4 K-chunks.
// C[M][256] = A[M][256] @ W[256][256]^T + bias. grid.z selects (W,bias,C,scale)
// so QKV runs as one launch.
// ---------------------------------------------------------------------------
#define GLDH 72
#define GSTGB (128 * GLDH * 2)            // bytes per matrix per stage
#define HG_SMEM (4 * GSTGB)               // A0,A1,W0,W1

template<bool RELU, bool HALF_OUT>
__global__ __launch_bounds__(256) void hgemm_h(const __half* __restrict__ A,
                                               const __half* W0, const __half* W1, const __half* W2,
                                               const float* b0, const float* b1, const float* b2,
                                               void* C0, void* C1, void* C2,
                                               float s0, float s1, float s2) {
    extern __shared__ __align__(16) char smraw[];
    const int z = blockIdx.z;
    const __half* W   = (z == 0) ? W0 : (z == 1) ? W1 : W2;
    const float* bias = (z == 0) ? b0 : (z == 1) ? b1 : b2;
    void* Cv          = (z == 0) ? C0 : (z == 1) ? C1 : C2;
    const float scale = (z == 0) ? s0 : (z == 1) ? s1 : s2;

    const uint32_t sA = smem_u32(smraw);              // stages at +0, +GSTGB
    const uint32_t sW = sA + 2 * GSTGB;               // stages at +0, +GSTGB
    const int tid  = threadIdx.x;
    const int warp = tid >> 5, lane = tid & 31;
    const int wm = warp & 3;
    const int wn = warp >> 2;
    const int m0 = blockIdx.y * 128;
    const int n0 = blockIdx.x * 128;

    float acc[2][8][4] = {};

    const uint32_t aAddr0 = sA + ((wm * 32 + (lane & 15)) * GLDH + (lane >> 4) * 8) * 2;
    const uint32_t wAddr0 = sW + ((wn * 64 + (lane & 7) + ((lane >> 4) & 1) * 8) * GLDH + ((lane >> 3) & 1) * 8) * 2;

    // prologue: chunk 0 -> stage 0
    for (int i = tid; i < 1024; i += 256) {
        int r = i >> 3, c8 = (i & 7) * 8;
        cpa16(sA + (r * GLDH + c8) * 2, A + (size_t)(m0 + r) * 256 + c8);
        cpa16(sW + (r * GLDH + c8) * 2, W + (size_t)(n0 + r) * 256 + c8);
    }
    cpa_commit();

    for (int kci = 0; kci < 4; kci++) {
        if (kci < 3) {
            const uint32_t so = ((kci + 1) & 1) * GSTGB;
            const int kc = (kci + 1) * 64;
            for (int i = tid; i < 1024; i += 256) {
                int r = i >> 3, c8 = (i & 7) * 8;
                cpa16(sA + so + (r * GLDH + c8) * 2, A + (size_t)(m0 + r) * 256 + kc + c8);
                cpa16(sW + so + (r * GLDH + c8) * 2, W + (size_t)(n0 + r) * 256 + kc + c8);
            }
        }
        cpa_commit();
        cpa_wait<1>();
        __syncthreads();

        const uint32_t so = (kci & 1) * GSTGB;
        const uint32_t aAddr = aAddr0 + so, wAddr = wAddr0 + so;
        #pragma unroll
        for (int kk = 0; kk < 4; kk++) {
            uint32_t a[2][4];
            ldsm4(a[0][0], a[0][1], a[0][2], a[0][3], aAddr + kk * 32);
            ldsm4(a[1][0], a[1][1], a[1][2], a[1][3], aAddr + 16 * GLDH * 2 + kk * 32);
            #pragma unroll
            for (int j = 0; j < 4; j++) {
                uint32_t b0r, b1r, b2r, b3r;
                ldsm4(b0r, b1r, b2r, b3r, wAddr + j * 16 * GLDH * 2 + kk * 32);
                mma16816(acc[0][2 * j],     a[0][0], a[0][1], a[0][2], a[0][3], b0r, b1r);
                mma16816(acc[0][2 * j + 1], a[0][0], a[0][1], a[0][2], a[0][3], b2r, b3r);
                mma16816(acc[1][2 * j],     a[1][0], a[1][1], a[1][2], a[1][3], b0r, b1r);
                mma16816(acc[1][2 * j + 1], a[1][0], a[1][1], a[1][2], a[1][3], b2r, b3r);
            }
        }
        __syncthreads();
    }

    const int g = lane >> 2, qd = lane & 3;
    #pragma unroll
    for (int s = 0; s < 2; s++) {
        int row0 = m0 + wm * 32 + s * 16 + g;
        #pragma unroll
        for (int j = 0; j < 8; j++) {
            int col = n0 + wn * 64 + j * 8 + qd * 2;
            float bb0 = bias[col], bb1 = bias[col + 1];
            float v00 = acc[s][j][0] + bb0, v01 = acc[s][j][1] + bb1;
            float v10 = acc[s][j][2] + bb0, v11 = acc[s][j][3] + bb1;
            if (RELU) {
                v00 = fmaxf(v00, 0.0f); v01 = fmaxf(v01, 0.0f);
                v10 = fmaxf(v10, 0.0f); v11 = fmaxf(v11, 0.0f);
            }
            if (HALF_OUT) {
                *(uint32_t*)((__half*)Cv + (size_t)row0 * 256 + col)       = packh2(v00 * scale, v01 * scale);
                *(uint32_t*)((__half*)Cv + (size_t)(row0 + 8) * 256 + col) = packh2(v10 * scale, v11 * scale);
            } else {
                float2 f0 = {v00, v01}, f1 = {v10, v11};
                *(float2*)((float*)Cv + (size_t)row0 * 256 + col)       = f0;
                *(float2*)((float*)Cv + (size_t)(row0 + 8) * 256 + col) = f1;
            }
        }
    }
}

// ---------------------------------------------------------------------------
// Flash attention (round-7 proven core: fp16 mma, online softmax, cp.async
// double-buffered K/V, Br=128/Bc=64, one wave) + FUSED LN1 epilogue:
// writes ghh = LayerNorm(x + attn_out) in fp16 directly.
// ---------------------------------------------------------------------------
#define LDH 264
#define BRQ 128
#define QTILEH (BRQ * LDH)
#define TILEH (64 * LDH)
#define STGH  (2 * TILEH)
#define FLASH_SMEM ((QTILEH + 2 * STGH) * (int)sizeof(__half))
#define L2E 1.44269504f

__global__ __launch_bounds__(256, 1) void flash_h(const __half* __restrict__ Q,
                                                  const __half* __restrict__ K,
                                                  const __half* __restrict__ V,
                                                  const float* __restrict__ X,
                                                  const float* __restrict__ g1,
                                                  const float* __restrict__ be1,
                                                  __half* __restrict__ H) {
    extern __shared__ __half sm[];
    __half* sQ  = sm;
    __half* sK0 = sm + QTILEH;
    __half* sV0 = sK0 + TILEH;

    const int b  = blockIdx.y;
    const int q0 = blockIdx.x * BRQ;
    const int tid = threadIdx.x;
    const int warp = tid >> 5;
    const int lane = tid & 31;
    const int g  = lane >> 2;
    const int qd = lane & 3;

    const __half* Qb = Q + ((size_t)b * SS + q0) * DD;
    const __half* Kb = K + (size_t)b * SS * DD;
    const __half* Vb = V + (size_t)b * SS * DD;

    for (int c = tid; c < 4096; c += 256) {
        int r = c >> 5, co = (c & 31) * 8;
        cpa16(smem_u32(sQ + r * LDH + co), Qb + (size_t)r * 256 + co);
    }
    {
        const uint32_t kDst = smem_u32(sK0);
        for (int c = tid; c < 2048; c += 256) {
            int r = c >> 5, co = (c & 31) * 8;
            cpa16(kDst + (r * LDH + co) * 2,         Kb + (size_t)r * 256 + co);
            cpa16(kDst + (TILEH + r * LDH + co) * 2, Vb + (size_t)r * 256 + co);
        }
        cpa_commit();
    }

    float o[32][4];
    #pragma unroll
    for (int t = 0; t < 32; t++) { o[t][0] = 0; o[t][1] = 0; o[t][2] = 0; o[t][3] = 0; }
    float m0 = -1e30f, m1 = -1e30f, l0 = 0.0f, l1 = 0.0f;

    const uint32_t aBase  = smem_u32(sQ + (warp * 16 + (lane & 15)) * LDH + (lane >> 4) * 8);
    const uint32_t kBase0 = smem_u32(sK0 + ((lane & 7) + ((lane >> 4) & 1) * 8) * LDH + ((lane >> 3) & 1) * 8);
    const uint32_t vBase0 = smem_u32(sV0 + (lane & 15) * LDH + (lane >> 4) * 8);
    const uint32_t kDst0  = smem_u32(sK0);

    for (int ti = 0; ti < SS / 64; ti++) {
        if (ti + 1 < SS / 64) {
            const uint32_t kDst = kDst0 + ((ti + 1) & 1) * STGH * 2;
            const __half* Kn = Kb + (size_t)(ti + 1) * 64 * 256;
            const __half* Vn = Vb + (size_t)(ti + 1) * 64 * 256;
            for (int c = tid; c < 2048; c += 256) {
                int r = c >> 5, co = (c & 31) * 8;
                cpa16(kDst + (r * LDH + co) * 2,         Kn + (size_t)r * 256 + co);
                cpa16(kDst + (TILEH + r * LDH + co) * 2, Vn + (size_t)r * 256 + co);
            }
        }
        cpa_commit();
        cpa_wait<1>();
        __syncthreads();

        const uint32_t kBase = kBase0 + (ti & 1) * STGH * 2;
        const uint32_t vBase = vBase0 + (ti & 1) * STGH * 2;

        // ---- S = Q K^T ----
        float s[8][4];
        #pragma unroll
        for (int j = 0; j < 8; j++) { s[j][0] = 0; s[j][1] = 0; s[j][2] = 0; s[j][3] = 0; }

        #pragma unroll
        for (int kk = 0; kk < 16; kk++) {
            uint32_t a0, a1, a2, a3;
            ldsm4(a0, a1, a2, a3, aBase + kk * 32);
            #pragma unroll
            for (int jj = 0; jj < 4; jj++) {
                uint32_t k0, k1, k2, k3;
                ldsm4(k0, k1, k2, k3, kBase + jj * 16 * LDH * 2 + kk * 32);
                mma16816(s[2 * jj],     a0, a1, a2, a3, k0, k1);
                mma16816(s[2 * jj + 1], a0, a1, a2, a3, k2, k3);
            }
        }

        // ---- online softmax ----
        float rmax0 = -1e30f, rmax1 = -1e30f;
        #pragma unroll
        for (int j = 0; j < 8; j++) {
            rmax0 = fmaxf(rmax0, fmaxf(s[j][0], s[j][1]));
            rmax1 = fmaxf(rmax1, fmaxf(s[j][2], s[j][3]));
        }
        rmax0 = fmaxf(rmax0, __shfl_xor_sync(0xffffffffu, rmax0, 1));
        rmax0 = fmaxf(rmax0, __shfl_xor_sync(0xffffffffu, rmax0, 2));
        rmax1 = fmaxf(rmax1, __shfl_xor_sync(0xffffffffu, rmax1, 1));
        rmax1 = fmaxf(rmax1, __shfl_xor_sync(0xffffffffu, rmax1, 2));

        float mn0 = fmaxf(m0, rmax0), mn1 = fmaxf(m1, rmax1);
        float corr0 = exp2f((m0 - mn0) * L2E);
        float corr1 = exp2f((m1 - mn1) * L2E);
        m0 = mn0; m1 = mn1;

        uint32_t pl[8], ph[8];
        float rs0 = 0.0f, rs1 = 0.0f;
        #pragma unroll
        for (int j = 0; j < 8; j++) {
            float p0 = exp2f((s[j][0] - mn0) * L2E);
            float p1 = exp2f((s[j][1] - mn0) * L2E);
            float p2 = exp2f((s[j][2] - mn1) * L2E);
            float p3 = exp2f((s[j][3] - mn1) * L2E);
            rs0 += p0 + p1; rs1 += p2 + p3;
            pl[j] = packh2(p0, p1);
            ph[j] = packh2(p2, p3);
        }
        rs0 += __shfl_xor_sync(0xffffffffu, rs0, 1);
        rs0 += __shfl_xor_sync(0xffffffffu, rs0, 2);
        rs1 += __shfl_xor_sync(0xffffffffu, rs1, 1);
        rs1 += __shfl_xor_sync(0xffffffffu, rs1, 2);
        l0 = l0 * corr0 + rs0;
        l1 = l1 * corr1 + rs1;

        #pragma unroll
        for (int t = 0; t < 32; t++) {
            o[t][0] *= corr0; o[t][1] *= corr0;
            o[t][2] *= corr1; o[t][3] *= corr1;
        }

        // ---- O += P V ----
        #pragma unroll
        for (int kk2 = 0; kk2 < 4; kk2++) {
            uint32_t a0 = pl[2 * kk2], a1 = ph[2 * kk2];
            uint32_t a2 = pl[2 * kk2 + 1], a3 = ph[2 * kk2 + 1];
            uint32_t vrow = vBase + kk2 * 16 * LDH * 2;
            #pragma unroll
            for (int nj = 0; nj < 16; nj++) {
                uint32_t v0, v1, v2, v3;
                ldsm4t(v0, v1, v2, v3, vrow + nj * 32);
                mma16816(o[2 * nj],     a0, a1, a2, a3, v0, v1);
                mma16816(o[2 * nj + 1], a0, a1, a2, a3, v2, v3);
            }
        }
        __syncthreads();
    }

    // ---- fused LN1 epilogue: H = LayerNorm(x + O/l) * g1 + be1, fp16 out ----
    float inv0 = 1.0f / l0, inv1 = 1.0f / l1;
    const size_t grow0 = (size_t)(b * SS + q0 + warp * 16 + g);
    const float* x0 = X + grow0 * 256;
    const float* x1 = x0 + 8 * 256;

    // pass 1: mean / mean-square of v = x + o*inv (E[v^2]-mu^2 one-pass)
    float s0 = 0.0f, ss0 = 0.0f, s1 = 0.0f, ss1 = 0.0f;
    #pragma unroll
    for (int j = 0; j < 32; j++) {
        int col = j * 8 + qd * 2;
        float2 xa = *(const float2*)(x0 + col);
        float2 xb = *(const float2*)(x1 + col);
        float va0 = xa.x + o[j][0] * inv0, va1 = xa.y + o[j][1] * inv0;
        float vb0 = xb.x + o[j][2] * inv1, vb1 = xb.y + o[j][3] * inv1;
        s0 += va0 + va1; ss0 += va0 * va0 + va1 * va1;
        s1 += vb0 + vb1; ss1 += vb0 * vb0 + vb1 * vb1;
    }
    s0  += __shfl_xor_sync(0xffffffffu, s0, 1);  s0  += __shfl_xor_sync(0xffffffffu, s0, 2);
    ss0 += __shfl_xor_sync(0xffffffffu, ss0, 1); ss0 += __shfl_xor_sync(0xffffffffu, ss0, 2);
    s1  += __shfl_xor_sync(0xffffffffu, s1, 1);  s1  += __shfl_xor_sync(0xffffffffu, s1, 2);
    ss1 += __shfl_xor_sync(0xffffffffu, ss1, 1); ss1 += __shfl_xor_sync(0xffffffffu, ss1, 2);
    float mu0 = s0 * (1.0f / 256.0f), mu1 = s1 * (1.0f / 256.0f);
    float rstd0 = rsqrtf(fmaxf(ss0 * (1.0f / 256.0f) - mu0 * mu0, 0.0f) + 1e-5f);
    float rstd1 = rsqrtf(fmaxf(ss1 * (1.0f / 256.0f) - mu1 * mu1, 0.0f) + 1e-5f);

    // pass 2: normalize, affine, emit fp16
    __half* h0 = H + grow0 * 256;
    __half* h1 = h0 + 8 * 256;
    #pragma unroll
    for (int j = 0; j < 32; j++) {
        int col = j * 8 + qd * 2;
        float2 xa = *(const float2*)(x0 + col);
        float2 xb = *(const float2*)(x1 + col);
        float2 gg = *(const float2*)(g1 + col);
        float2 bb = *(const float2*)(be1 + col);
        float va0 = xa.x + o[j][0] * inv0, va1 = xa.y + o[j][1] * inv0;
        float vb0 = xb.x + o[j][2] * inv1, vb1 = xb.y + o[j][3] * inv1;
        float w00 = (va0 - mu0) * rstd0 * gg.x + bb.x;
        float w01 = (va1 - mu0) * rstd0 * gg.y + bb.y;
        float w10 = (vb0 - mu1) * rstd1 * gg.x + bb.x;
        float w11 = (vb1 - mu1) * rstd1 * gg.y + bb.y;
        *(uint32_t*)(h0 + col) = packh2(w00, w01);
        *(uint32_t*)(h1 + col) = packh2(w10, w11);
    }
}

// ---------------------------------------------------------------------------
// LayerNorm(X + R) * g + be (fp32 out) — used only for LN2
// ---------------------------------------------------------------------------
__global__ __launch_bounds__(256) void ln_k(const float* __restrict__ X,
                                            const float* __restrict__ R,
                                            const float* __restrict__ g,
                                            const float* __restrict__ be,
                                            float* __restrict__ out) {
    int row  = (blockIdx.x * blockDim.x + threadIdx.x) >> 5;
    int lane = threadIdx.x & 31;
    const float* xr = X + (size_t)row * DD;
    const float* rr = R + (size_t)row * DD;

    float v[8];
    float s = 0.0f;
    #pragma unroll
    for (int t = 0; t < 8; t++) {
        int d = t * 32 + lane;
        v[t] = xr[d] + rr[d];
        s += v[t];
    }
    #pragma unroll
    for (int o = 16; o; o >>= 1) s += __shfl_xor_sync(0xffffffffu, s, o);
    float mu = s * (1.0f / 256.0f);

    float var = 0.0f;
    #pragma unroll
    for (int t = 0; t < 8; t++) { float dv = v[t] - mu; var += dv * dv; }
    #pragma unroll
    for (int o = 16; o; o >>= 1) var += __shfl_xor_sync(0xffffffffu, var, o);
    var *= (1.0f / 256.0f);
    float rstd = rsqrtf(var + 1e-5f);

    #pragma unroll
    for (int t = 0; t < 8; t++) {
        int d = t * 32 + lane;
        out[(size_t)row * DD + d] = (v[t] - mu) * rstd * g[d] + be[d];
    }
}

// ---------------------------------------------------------------------------
extern "C" void kernel_launch(void* const* d_in, const int* in_sizes, int n_in,
                              void* d_out, int out_size) {
    (void)in_sizes; (void)n_in; (void)out_size;
    const float* x  = (const float*)d_in[0];
    const float* Wq = (const float*)d_in[1];
    const float* bq = (const float*)d_in[2];
    const float* Wk = (const float*)d_in[3];
    const float* bk = (const float*)d_in[4];
    const float* Wv = (const float*)d_in[5];
    const float* bv = (const float*)d_in[6];
    const float* Wl = (const float*)d_in[7];
    const float* bl = (const float*)d_in[8];
    const float* g1 = (const float*)d_in[9];
    const float* be1= (const float*)d_in[10];
    const float* g2 = (const float*)d_in[11];
    const float* be2= (const float*)d_in[12];
    float* out = (float*)d_out;

    __half *gxh, *gw, *gq, *gk, *gv, *ghh, *gth;
    float *gt2;
    cudaGetSymbolAddress((void**)&gxh, g_xh);
    cudaGetSymbolAddress((void**)&gw,  g_w4);
    cudaGetSymbolAddress((void**)&gq,  g_qh);
    cudaGetSymbolAddress((void**)&gk,  g_kh);
    cudaGetSymbolAddress((void**)&gv,  g_vh);
    cudaGetSymbolAddress((void**)&ghh, g_hh);
    cudaGetSymbolAddress((void**)&gth, g_th);
    cudaGetSymbolAddress((void**)&gt2, g_t2);

    cudaFuncSetAttribute(flash_h, cudaFuncAttributeMaxDynamicSharedMemorySize, FLASH_SMEM);
    cudaFuncSetAttribute((const void*)hgemm_h<false, true >, cudaFuncAttributeMaxDynamicSharedMemorySize, HG_SMEM);
    cudaFuncSetAttribute((const void*)hgemm_h<true,  true >, cudaFuncAttributeMaxDynamicSharedMemorySize, HG_SMEM);
    cudaFuncSetAttribute((const void*)hgemm_h<false, false>, cudaFuncAttributeMaxDynamicSharedMemorySize, HG_SMEM);

    const __half* wq = gw;
    const __half* wk = gw + DD * DD;
    const __half* wv = gw + 2 * DD * DD;
    const __half* wl = gw + 3 * DD * DD;

    // fp32 -> fp16 staging
    cvt_x<<<ROWS * DD / (256 * 8), 256>>>(x, gxh);
    cvt_w<<<dim3(DD * DD / (256 * 8), 4), 256>>>(Wq, Wk, Wv, Wl, gw);

    // fused QKV projection (one launch, grid.z selects q/k/v)
    hgemm_h<false, true><<<dim3(2, 128, 3), 256, HG_SMEM>>>(
        gxh, wq, wk, wv, bq, bk, bv, gq, gk, gv, 0.0625f, 1.0f, 1.0f);

    // flash attention + fused LN1 -> ghh (fp16)
    flash_h<<<dim3(SS / BRQ, BB), 256, FLASH_SMEM>>>(gq, gk, gv, x, g1, be1, ghh);

    // MLP (same weight twice), cp.async-pipelined
    hgemm_h<true,  true ><<<dim3(2, 128, 1), 256, HG_SMEM>>>(
        ghh, wl, wl, wl, bl, bl, bl, gth, gth, gth, 1.0f, 1.0f, 1.0f);
    hgemm_h<false, false><<<dim3(2, 128, 1), 256, HG_SMEM>>>(
        gth, wl, wl, wl, bl, bl, bl, gt2, gt2, gt2, 1.0f, 1.0f, 1.0f);

    ln_k<<<ROWS / 8, 256>>>(x, gt2, g2, be2, out);
}